// round 16
// baseline (speedup 1.0000x reference)
#include <cuda_runtime.h>
#include <cuda_fp16.h>
#include <math.h>
#include <stdint.h>

#define NN     16384
#define IN_F   256
#define OUT_F  128
#define ALPHA  0.2f
#define LOG2E  1.4426950408889634f

// ---------------- device-global scratch (no allocation) --------------------
__device__ float g_Q[NN * OUT_F];
__device__ float g_K[NN * OUT_F];
__device__ float g_V[NN * OUT_F];
__device__ __half g_Qh[NN * OUT_F];
__device__ __half g_Ql[NN * OUT_F];
// K fragments: [blk 256][kk 8][j 8][lane 32] uint4 = (bh0,bh1,bl0,bl1)  (8 MB)
__device__ __align__(16) uint4 g_Kp[256 * 2048];
// V fragments PAIRED: [blk 256][kk 4][dtp 8][lane 32] uint4 = frag(dt=2dtp).xy, frag(dt=2dtp+1).xy
__device__ __align__(16) uint4 g_Vp[256 * 1024];

// ---------------- helpers ----------------------------------------------
__device__ __forceinline__ uint32_t smem_u32(const void* p) {
    uint32_t a;
    asm("{ .reg .u64 t; cvta.to.shared.u64 t, %1; cvt.u32.u64 %0, t; }" : "=r"(a) : "l"(p));
    return a;
}
__device__ __forceinline__ float ex2f(float x) {
    float y; asm("ex2.approx.f32 %0, %1;" : "=f"(y) : "f"(x)); return y;
}
__device__ __forceinline__ void cpa16(uint32_t s, const void* g) {
    asm volatile("cp.async.cg.shared.global [%0], [%1], 16;" :: "r"(s), "l"(g));
}
#define CPA_COMMIT() asm volatile("cp.async.commit_group;" ::: "memory")
#define CPA_WAIT1()  asm volatile("cp.async.wait_group 1;" ::: "memory")

// m16n8k16 fp16 mma, fp32 accumulate
#define MMA4(c, a, b0v, b1v) \
    asm volatile("mma.sync.aligned.m16n8k16.row.col.f32.f16.f16.f32 " \
        "{%0,%1,%2,%3},{%4,%5,%6,%7},{%8,%9},{%0,%1,%2,%3};" \
        : "+f"((c)[0]), "+f"((c)[1]), "+f"((c)[2]), "+f"((c)[3]) \
        : "r"((a)[0]), "r"((a)[1]), "r"((a)[2]), "r"((a)[3]), "r"(b0v), "r"(b1v))

__device__ __forceinline__ uint32_t h2u(__half2 h) {
    uint32_t u; asm("mov.b32 %0, %1;" : "=r"(u) : "r"(*(uint32_t*)&h)); return u;
}
__device__ __forceinline__ void split_h(float x, __half& h, __half& l) {
    h = __float2half_rn(x);
    l = __float2half_rn(x - __half2float(h));
}

// ---------------------------------------------------------------------------
// Kernel 1: merged QKV projection.  grid = NN/64 = 256 CTAs, 256 threads.
// h tile [64 x 256] loaded ONCE into swizzled smem; 3 GEMMs reuse it.
// Dynamic smem: hs 64x256 fp32 (swizzled) + ws 64x128 fp32 = 96 KB -> 2 CTAs/SM.
// ---------------------------------------------------------------------------
#define QKV_SMEM ((64 * 256 + 64 * 128) * 4)

__global__ __launch_bounds__(256) void qkv_kernel(
    const float* __restrict__ h, const float* __restrict__ Wq,
    const float* __restrict__ Wk, const float* __restrict__ Wv)
{
    extern __shared__ float qsm[];
    float* hsf = qsm;                   // [64][256] with XOR swizzle
    float* wsf = qsm + 64 * 256;        // [64][128] plain

    const int tid = threadIdx.x, ri = tid >> 4, ci = tid & 15;
    const int row0 = blockIdx.x * 64;

    // load h tile once: 4096 float4, 16 per thread; swizzle cols by row/4
#pragma unroll
    for (int l = 0; l < 16; l++) {
        int idx = tid + l * 256;
        int r = idx >> 6, c4 = (idx & 63) * 4;
        int sc = c4 ^ (((r >> 2) & 7) << 2);
        *(float4*)&hsf[r * 256 + sc] = *(const float4*)&h[(size_t)(row0 + r) * IN_F + c4];
    }

    const float* Ws[3]  = {Wq, Wk, Wv};
    float*       Out[3] = {g_Q, g_K, g_V};
    const int swz = (ri & 7) << 2;      // thread's 4 rows share (row>>2)&7 == ri&7

    for (int w = 0; w < 3; w++) {
        const float* W = Ws[w];
        float acc[4][8];
#pragma unroll
        for (int a = 0; a < 4; a++)
#pragma unroll
            for (int b = 0; b < 8; b++) acc[a][b] = 0.f;

        for (int kc = 0; kc < IN_F; kc += 64) {
            __syncthreads();            // prior use of ws (and hs fill) complete
#pragma unroll
            for (int l = 0; l < 8; l++) {
                int idx = tid + l * 256, r = idx >> 5, c4 = (idx & 31) * 4;
                *(float4*)&wsf[r * 128 + c4] = *(const float4*)&W[(size_t)(kc + r) * OUT_F + c4];
            }
            __syncthreads();

#pragma unroll 4
            for (int k = 0; k < 64; k += 4) {
                float a_[4][4];
#pragma unroll
                for (int r = 0; r < 4; r++)
                    *(float4*)a_[r] = *(const float4*)&hsf[(ri * 4 + r) * 256 + ((kc + k) ^ swz)];
#pragma unroll
                for (int kq = 0; kq < 4; kq++) {
                    float4 b0 = *(const float4*)&wsf[(k + kq) * 128 + ci * 8];
                    float4 b1 = *(const float4*)&wsf[(k + kq) * 128 + ci * 8 + 4];
                    float bb[8] = {b0.x, b0.y, b0.z, b0.w, b1.x, b1.y, b1.z, b1.w};
#pragma unroll
                    for (int j = 0; j < 8; j++) {
                        acc[0][j] = fmaf(a_[0][kq], bb[j], acc[0][j]);
                        acc[1][j] = fmaf(a_[1][kq], bb[j], acc[1][j]);
                        acc[2][j] = fmaf(a_[2][kq], bb[j], acc[2][j]);
                        acc[3][j] = fmaf(a_[3][kq], bb[j], acc[3][j]);
                    }
                }
            }
        }
#pragma unroll
        for (int a = 0; a < 4; a++) {
            int r = row0 + ri * 4 + a;
            float4 v0 = {acc[a][0], acc[a][1], acc[a][2], acc[a][3]};
            float4 v1 = {acc[a][4], acc[a][5], acc[a][6], acc[a][7]};
            *(float4*)&Out[w][(size_t)r * OUT_F + ci * 8]     = v0;
            *(float4*)&Out[w][(size_t)r * OUT_F + ci * 8 + 4] = v1;
        }
    }
}

// ---------------------------------------------------------------------------
// Kernel 2: pack Q (fp16 hi/lo rows), K (hi/lo B-fragments), V (paired B-frags)
// ---------------------------------------------------------------------------
__global__ __launch_bounds__(256) void pack_kernel() {
    const int b = blockIdx.x, tid = threadIdx.x;

    for (int idx = tid; idx < 64 * 128; idx += 256) {
        int r = b * 64 + (idx >> 7), c = idx & 127;
        float x = g_Q[(size_t)r * 128 + c];
        __half h, l; split_h(x, h, l);
        g_Qh[(size_t)r * 128 + c] = h;
        g_Ql[(size_t)r * 128 + c] = l;
    }
    // K fragments: thread holds K[n=8j+g][k=16kk+2t+{0,1}] (x) and k+8 (y); lo in z,w
    for (int idx = tid; idx < 2048; idx += 256) {
        int kk = idx >> 8, j = (idx >> 5) & 7, lane = idx & 31;
        int g = lane >> 2, t = lane & 3;
        int n = b * 64 + 8 * j + g;
        int d = 16 * kk + 2 * t;
        const float* kr = &g_K[(size_t)n * 128];
        __half h0, l0, h1, l1, h2, l2, h3, l3;
        split_h(kr[d],     h0, l0); split_h(kr[d + 1], h1, l1);
        split_h(kr[d + 8], h2, l2); split_h(kr[d + 9], h3, l3);
        uint4 u;
        u.x = h2u(__halves2half2(h0, h1));
        u.y = h2u(__halves2half2(h2, h3));
        u.z = h2u(__halves2half2(l0, l1));
        u.w = h2u(__halves2half2(l2, l3));
        g_Kp[(size_t)b * 2048 + idx] = u;
    }
    // V fragments paired: (x,y) = frag for dt=2dtp (dim=16dtp+g), (z,w) = dt=2dtp+1 (dim+8)
    for (int idx = tid; idx < 1024; idx += 256) {
        int kk = idx >> 8, dtp = (idx >> 5) & 7, lane = idx & 31;
        int g = lane >> 2, t = lane & 3;
        int k0 = b * 64 + 16 * kk + 2 * t;
        int dim0 = 16 * dtp + g, dim1 = dim0 + 8;
        uint4 u;
        u.x = h2u(__halves2half2(__float2half_rn(g_V[(size_t)k0 * 128 + dim0]),
                                 __float2half_rn(g_V[(size_t)(k0 + 1) * 128 + dim0])));
        u.y = h2u(__halves2half2(__float2half_rn(g_V[(size_t)(k0 + 8) * 128 + dim0]),
                                 __float2half_rn(g_V[(size_t)(k0 + 9) * 128 + dim0])));
        u.z = h2u(__halves2half2(__float2half_rn(g_V[(size_t)k0 * 128 + dim1]),
                                 __float2half_rn(g_V[(size_t)(k0 + 1) * 128 + dim1])));
        u.w = h2u(__halves2half2(__float2half_rn(g_V[(size_t)(k0 + 8) * 128 + dim1]),
                                 __float2half_rn(g_V[(size_t)(k0 + 9) * 128 + dim1])));
        g_Vp[(size_t)b * 1024 + idx] = u;
    }
}

// ---------------------------------------------------------------------------
// Kernel 3: flash attention via mma.sync.  128 CTAs x 256 thr (8 warps x 16 rows).
// ---------------------------------------------------------------------------
#define SMEM_KV   49152                 // Kp 32KB + Vp 16KB
#define ADJ_ROWB  272                   // 64 ints padded to 68 (bank spread)
#define SMEM_ADJ  (128 * ADJ_ROWB)      // 34816
#define SMEM_DYN  (2 * SMEM_KV + 2 * SMEM_ADJ)

__device__ __forceinline__ void prefetch_tiles(uint32_t smb, int buf, int blk,
                                               const int* adj, int qrow0, int tid)
{
    uint32_t dk = smb + (uint32_t)buf * SMEM_KV;
    const unsigned char* srcK = (const unsigned char*)g_Kp + (size_t)blk * 32768;
    const unsigned char* srcV = (const unsigned char*)g_Vp + (size_t)blk * 16384;
#pragma unroll
    for (int i = 0; i < 8; i++) { int o = (tid + i * 256) * 16; cpa16(dk + o, srcK + o); }
#pragma unroll
    for (int i = 0; i < 4; i++) { int o = (tid + i * 256) * 16; cpa16(dk + 32768 + o, srcV + o); }
    uint32_t da = smb + 2 * SMEM_KV + (uint32_t)buf * SMEM_ADJ;
#pragma unroll
    for (int i = 0; i < 8; i++) {
        int c = tid + i * 256;                 // 2048 x 16B chunks
        int row = c >> 4, c16 = c & 15;
        const int* src = adj + (size_t)(qrow0 + row) * NN + blk * 64 + c16 * 4;
        cpa16(da + row * ADJ_ROWB + c16 * 16, src);
    }
}

__global__ __launch_bounds__(256, 1) void attn_kernel(
    const int* __restrict__ adj, float* __restrict__ out)
{
    extern __shared__ __align__(16) unsigned char smraw[];
    const int tid = threadIdx.x, w = tid >> 5, lane = tid & 31;
    const int g = lane >> 2, t = lane & 3;
    const int qrow0 = blockIdx.x * 128;
    const int r0 = qrow0 + w * 16 + g, r1 = r0 + 8;
    const uint32_t smb = smem_u32(smraw);

    prefetch_tiles(smb, 0, 0, adj, qrow0, tid); CPA_COMMIT();
    prefetch_tiles(smb, 1, 1, adj, qrow0, tid); CPA_COMMIT();

    // Q fragments (held in registers for the whole kernel)
    uint32_t qh[8][4], ql[8][4];
#pragma unroll
    for (int kk = 0; kk < 8; kk++) {
        int c = kk * 16 + 2 * t;
        qh[kk][0] = *(const uint32_t*)&g_Qh[(size_t)r0 * 128 + c];
        qh[kk][1] = *(const uint32_t*)&g_Qh[(size_t)r1 * 128 + c];
        qh[kk][2] = *(const uint32_t*)&g_Qh[(size_t)r0 * 128 + c + 8];
        qh[kk][3] = *(const uint32_t*)&g_Qh[(size_t)r1 * 128 + c + 8];
        ql[kk][0] = *(const uint32_t*)&g_Ql[(size_t)r0 * 128 + c];
        ql[kk][1] = *(const uint32_t*)&g_Ql[(size_t)r1 * 128 + c];
        ql[kk][2] = *(const uint32_t*)&g_Ql[(size_t)r0 * 128 + c + 8];
        ql[kk][3] = *(const uint32_t*)&g_Ql[(size_t)r1 * 128 + c + 8];
    }

    float o[16][4];
#pragma unroll
    for (int dt = 0; dt < 16; dt++)
#pragma unroll
        for (int i = 0; i < 4; i++) o[dt][i] = 0.f;
    float m0 = -1e30f, m1 = -1e30f, l0 = 0.f, l1 = 0.f;

    const int arow0 = (w * 16 + g) * (ADJ_ROWB / 8);       // int2 units
    const int arow1 = (w * 16 + g + 8) * (ADJ_ROWB / 8);

    for (int it = 0; it < 256; ++it) {
        CPA_WAIT1();
        __syncthreads();
        const int buf = it & 1;
        const uint4* khl  = (const uint4*)(smraw + buf * SMEM_KV);
        const uint4* vbf4 = (const uint4*)(smraw + buf * SMEM_KV + 32768);
        const int2*  am   = (const int2*)(smraw + 2 * SMEM_KV + buf * SMEM_ADJ);

        // ---- S = Q K^T (3-term fp16 split, Kh frag reused) ----
        float s[8][4];
#pragma unroll
        for (int j = 0; j < 8; j++)
#pragma unroll
            for (int i = 0; i < 4; i++) s[j][i] = 0.f;
#pragma unroll
        for (int kk = 0; kk < 8; kk++) {
#pragma unroll
            for (int j = 0; j < 8; j++) {
                uint4 b = khl[(((kk << 3) + j) << 5) + lane];
                MMA4(s[j], qh[kk], b.x, b.y);
                MMA4(s[j], ql[kk], b.x, b.y);
                MMA4(s[j], qh[kk], b.z, b.w);
            }
        }

        // ---- leaky relu + adjacency mask + block max ----
        float bm0 = -3e38f, bm1 = -3e38f;
#pragma unroll
        for (int j = 0; j < 8; j++) {
            int2 a0 = am[arow0 + 4 * j + t];
            int2 a1 = am[arow1 + 4 * j + t];
            float v;
            v = s[j][0]; v = fmaxf(v, ALPHA * v); s[j][0] = a0.x ? v : -3e38f;
            v = s[j][1]; v = fmaxf(v, ALPHA * v); s[j][1] = a0.y ? v : -3e38f;
            v = s[j][2]; v = fmaxf(v, ALPHA * v); s[j][2] = a1.x ? v : -3e38f;
            v = s[j][3]; v = fmaxf(v, ALPHA * v); s[j][3] = a1.y ? v : -3e38f;
            bm0 = fmaxf(bm0, fmaxf(s[j][0], s[j][1]));
            bm1 = fmaxf(bm1, fmaxf(s[j][2], s[j][3]));
        }
        bm0 = fmaxf(bm0, __shfl_xor_sync(0xffffffffu, bm0, 1));
        bm0 = fmaxf(bm0, __shfl_xor_sync(0xffffffffu, bm0, 2));
        bm1 = fmaxf(bm1, __shfl_xor_sync(0xffffffffu, bm1, 1));
        bm1 = fmaxf(bm1, __shfl_xor_sync(0xffffffffu, bm1, 2));

        // ---- online-max update with warp-vote skip (ex2(0)==1 exactly) ----
        bool upd = (bm0 > m0) || (bm1 > m1);
        if (__any_sync(0xffffffffu, upd)) {
            float nm0 = fmaxf(m0, bm0), nm1 = fmaxf(m1, bm1);
            float fs0 = ex2f((m0 - nm0) * LOG2E);
            float fs1 = ex2f((m1 - nm1) * LOG2E);
            m0 = nm0; m1 = nm1;
            l0 *= fs0; l1 *= fs1;
#pragma unroll
            for (int dt = 0; dt < 16; dt++) {
                o[dt][0] *= fs0; o[dt][1] *= fs0;
                o[dt][2] *= fs1; o[dt][3] *= fs1;
            }
        }
        const float n0s = m0 * LOG2E, n1s = m1 * LOG2E;

        // ---- exp + convert to fp16 PV A-fragments (register-to-register) ----
        uint32_t pf[4][4];
        float ps0 = 0.f, ps1 = 0.f;
#pragma unroll
        for (int kk = 0; kk < 4; kk++) {
#pragma unroll
            for (int half = 0; half < 2; half++) {
                int j = 2 * kk + half;
                float p0 = ex2f(fmaf(s[j][0], LOG2E, -n0s));
                float p1 = ex2f(fmaf(s[j][1], LOG2E, -n0s));
                float p2 = ex2f(fmaf(s[j][2], LOG2E, -n1s));
                float p3 = ex2f(fmaf(s[j][3], LOG2E, -n1s));
                __half2 hA = __floats2half2_rn(p0, p1);
                __half2 hB = __floats2half2_rn(p2, p3);
                pf[kk][0 + 2 * half] = h2u(hA);
                pf[kk][1 + 2 * half] = h2u(hB);
                float2 fA = __half22float2(hA), fB = __half22float2(hB);
                ps0 += fA.x + fA.y;
                ps1 += fB.x + fB.y;
            }
        }
        l0 += ps0;
        l1 += ps1;

        // ---- O += P V (paired V frags: 2 MMAs per LDS.128) ----
#pragma unroll
        for (int kk = 0; kk < 4; kk++) {
#pragma unroll
            for (int dtp = 0; dtp < 8; dtp++) {
                uint4 v = vbf4[(((kk << 3) + dtp) << 5) + lane];
                MMA4(o[2 * dtp],     pf[kk], v.x, v.y);
                MMA4(o[2 * dtp + 1], pf[kk], v.z, v.w);
            }
        }

        __syncthreads();
        if (it + 2 < 256)
            prefetch_tiles(smb, buf, it + 2, adj, qrow0, tid);
        CPA_COMMIT();
    }

    // ---- epilogue: reduce l across quad, normalize, ELU, store ----
    l0 += __shfl_xor_sync(0xffffffffu, l0, 1);
    l0 += __shfl_xor_sync(0xffffffffu, l0, 2);
    l1 += __shfl_xor_sync(0xffffffffu, l1, 1);
    l1 += __shfl_xor_sync(0xffffffffu, l1, 2);
    const float i0 = 1.f / l0, i1 = 1.f / l1;
#pragma unroll
    for (int dt = 0; dt < 16; dt++) {
        float x0 = o[dt][0] * i0, x1 = o[dt][1] * i0;
        float x2 = o[dt][2] * i1, x3 = o[dt][3] * i1;
        x0 = (x0 > 0.f) ? x0 : (__expf(x0) - 1.f);
        x1 = (x1 > 0.f) ? x1 : (__expf(x1) - 1.f);
        x2 = (x2 > 0.f) ? x2 : (__expf(x2) - 1.f);
        x3 = (x3 > 0.f) ? x3 : (__expf(x3) - 1.f);
        int c = 8 * dt + 2 * t;
        *(float2*)&out[(size_t)r0 * 128 + c] = make_float2(x0, x1);
        *(float2*)&out[(size_t)r1 * 128 + c] = make_float2(x2, x3);
    }
}

// ---------------------------------------------------------------------------
extern "C" void kernel_launch(void* const* d_in, const int* in_sizes, int n_in,
                              void* d_out, int out_size)
{
    const float* h   = (const float*)d_in[0];
    const int*   adj = (const int*)  d_in[1];
    const float* Wq  = (const float*)d_in[2];
    const float* Wk  = (const float*)d_in[3];
    const float* Wv  = (const float*)d_in[4];
    float*       out = (float*)d_out;
    (void)in_sizes; (void)n_in; (void)out_size;

    cudaFuncSetAttribute(qkv_kernel,  cudaFuncAttributeMaxDynamicSharedMemorySize, QKV_SMEM);
    cudaFuncSetAttribute(attn_kernel, cudaFuncAttributeMaxDynamicSharedMemorySize, SMEM_DYN);

    qkv_kernel<<<NN / 64, 256, QKV_SMEM>>>(h, Wq, Wk, Wv);
    pack_kernel<<<256, 256>>>();
    attn_kernel<<<NN / 128, 256, SMEM_DYN>>>(adj, out);
}

// round 17
// speedup vs baseline: 1.0889x; 1.0889x over previous
#include <cuda_runtime.h>
#include <cuda_fp16.h>
#include <math.h>
#include <stdint.h>

#define NN     16384
#define IN_F   256
#define OUT_F  128
#define ALPHA  0.2f
#define LOG2E  1.4426950408889634f
#define THRD   11.15f

__device__ float g_Q[NN * OUT_F];
__device__ float g_K[NN * OUT_F];
__device__ float g_V[NN * OUT_F];
__device__ __half g_Qh[NN * OUT_F];
__device__ __half g_Ql[NN * OUT_F];
__device__ __align__(16) uint4 g_Kp[256 * 2048];   // K hi/lo frags (validated layout)
__device__ __align__(16) uint4 g_Vp[256 * 1024];   // V paired frags (validated layout)
__device__ __align__(16) uint4 g_Kh2[256 * 1024];  // K hi-only, j-paired (pass 1)
__device__ __half g_Bmax[(size_t)NN * 256];        // [rowgrp][blk][row&15] leaky blockmax
__device__ float g_M[NN];                          // per-row leaky masked max (cheap)

__device__ __forceinline__ uint32_t smem_u32(const void* p) {
    uint32_t a;
    asm("{ .reg .u64 t; cvta.to.shared.u64 t, %1; cvt.u32.u64 %0, t; }" : "=r"(a) : "l"(p));
    return a;
}
__device__ __forceinline__ float ex2f(float x) {
    float y; asm("ex2.approx.f32 %0, %1;" : "=f"(y) : "f"(x)); return y;
}
__device__ __forceinline__ void cpa16(uint32_t s, const void* g) {
    asm volatile("cp.async.cg.shared.global [%0], [%1], 16;" :: "r"(s), "l"(g));
}
#define CPA_COMMIT() asm volatile("cp.async.commit_group;" ::: "memory")
#define CPA_WAIT1()  asm volatile("cp.async.wait_group 1;" ::: "memory")
#define MMA4(c, a, b0v, b1v) \
    asm volatile("mma.sync.aligned.m16n8k16.row.col.f32.f16.f16.f32 " \
        "{%0,%1,%2,%3},{%4,%5,%6,%7},{%8,%9},{%0,%1,%2,%3};" \
        : "+f"((c)[0]), "+f"((c)[1]), "+f"((c)[2]), "+f"((c)[3]) \
        : "r"((a)[0]), "r"((a)[1]), "r"((a)[2]), "r"((a)[3]), "r"(b0v), "r"(b1v))
__device__ __forceinline__ uint32_t h2u(__half2 h) {
    uint32_t u; asm("mov.b32 %0, %1;" : "=r"(u) : "r"(*(uint32_t*)&h)); return u;
}
__device__ __forceinline__ uint32_t pk(float a, float b) {
    return h2u(__halves2half2(__float2half_rn(a), __float2half_rn(b)));
}
__device__ __forceinline__ void split_h(float x, __half& h, __half& l) {
    h = __float2half_rn(x);
    l = __float2half_rn(x - __half2float(h));
}

// ---------------- Kernel 1: merged QKV (validated, ~140us) ------------------
#define QKV_SMEM ((64 * 256 + 64 * 128) * 4)
__global__ __launch_bounds__(256) void qkv_kernel(
    const float* __restrict__ h, const float* __restrict__ Wq,
    const float* __restrict__ Wk, const float* __restrict__ Wv)
{
    extern __shared__ float qsm[];
    float* hsf = qsm;
    float* wsf = qsm + 64 * 256;
    const int tid = threadIdx.x, ri = tid >> 4, ci = tid & 15;
    const int row0 = blockIdx.x * 64;
#pragma unroll
    for (int l = 0; l < 16; l++) {
        int idx = tid + l * 256, r = idx >> 6, c4 = (idx & 63) * 4;
        int sc = c4 ^ (((r >> 2) & 7) << 2);
        *(float4*)&hsf[r * 256 + sc] = *(const float4*)&h[(size_t)(row0 + r) * IN_F + c4];
    }
    const float* Ws[3]  = {Wq, Wk, Wv};
    float*       Out[3] = {g_Q, g_K, g_V};
    const int swz = (ri & 7) << 2;
    for (int w = 0; w < 3; w++) {
        const float* W = Ws[w];
        float acc[4][8];
#pragma unroll
        for (int a = 0; a < 4; a++)
#pragma unroll
            for (int b = 0; b < 8; b++) acc[a][b] = 0.f;
        for (int kc = 0; kc < IN_F; kc += 64) {
            __syncthreads();
#pragma unroll
            for (int l = 0; l < 8; l++) {
                int idx = tid + l * 256, r = idx >> 5, c4 = (idx & 31) * 4;
                *(float4*)&wsf[r * 128 + c4] = *(const float4*)&W[(size_t)(kc + r) * OUT_F + c4];
            }
            __syncthreads();
#pragma unroll 4
            for (int k = 0; k < 64; k += 4) {
                float a_[4][4];
#pragma unroll
                for (int r = 0; r < 4; r++)
                    *(float4*)a_[r] = *(const float4*)&hsf[(ri * 4 + r) * 256 + ((kc + k) ^ swz)];
#pragma unroll
                for (int kq = 0; kq < 4; kq++) {
                    float4 b0 = *(const float4*)&wsf[(k + kq) * 128 + ci * 8];
                    float4 b1 = *(const float4*)&wsf[(k + kq) * 128 + ci * 8 + 4];
                    float bb[8] = {b0.x, b0.y, b0.z, b0.w, b1.x, b1.y, b1.z, b1.w};
#pragma unroll
                    for (int j = 0; j < 8; j++) {
                        acc[0][j] = fmaf(a_[0][kq], bb[j], acc[0][j]);
                        acc[1][j] = fmaf(a_[1][kq], bb[j], acc[1][j]);
                        acc[2][j] = fmaf(a_[2][kq], bb[j], acc[2][j]);
                        acc[3][j] = fmaf(a_[3][kq], bb[j], acc[3][j]);
                    }
                }
            }
        }
#pragma unroll
        for (int a = 0; a < 4; a++) {
            int r = row0 + ri * 4 + a;
            float4 v0 = {acc[a][0], acc[a][1], acc[a][2], acc[a][3]};
            float4 v1 = {acc[a][4], acc[a][5], acc[a][6], acc[a][7]};
            *(float4*)&Out[w][(size_t)r * OUT_F + ci * 8]     = v0;
            *(float4*)&Out[w][(size_t)r * OUT_F + ci * 8 + 4] = v1;
        }
    }
}

// ---------------- Kernel 2: pack fragments ----------------------------------
__global__ __launch_bounds__(256) void pack_kernel() {
    const int b = blockIdx.x, tid = threadIdx.x;
    for (int idx = tid; idx < 64 * 128; idx += 256) {
        int r = b * 64 + (idx >> 7), c = idx & 127;
        float x = g_Q[(size_t)r * 128 + c];
        __half h, l; split_h(x, h, l);
        g_Qh[(size_t)r * 128 + c] = h;
        g_Ql[(size_t)r * 128 + c] = l;
    }
    for (int idx = tid; idx < 2048; idx += 256) {   // K hi/lo frags
        int kk = idx >> 8, j = (idx >> 5) & 7, lane = idx & 31;
        int g = lane >> 2, t = lane & 3;
        int n = b * 64 + 8 * j + g, d = 16 * kk + 2 * t;
        const float* kr = &g_K[(size_t)n * 128];
        __half h0, l0, h1, l1, h2, l2, h3, l3;
        split_h(kr[d],     h0, l0); split_h(kr[d + 1], h1, l1);
        split_h(kr[d + 8], h2, l2); split_h(kr[d + 9], h3, l3);
        uint4 u;
        u.x = h2u(__halves2half2(h0, h1)); u.y = h2u(__halves2half2(h2, h3));
        u.z = h2u(__halves2half2(l0, l1)); u.w = h2u(__halves2half2(l2, l3));
        g_Kp[(size_t)b * 2048 + idx] = u;
    }
    for (int idx = tid; idx < 1024; idx += 256) {   // K hi-only j-paired
        int kk = idx >> 7, jp = (idx >> 5) & 3, lane = idx & 31;
        int g = lane >> 2, t = lane & 3;
        int n0 = b * 64 + 16 * jp + g, n1 = n0 + 8, d = 16 * kk + 2 * t;
        const float* k0 = &g_K[(size_t)n0 * 128];
        const float* k1 = &g_K[(size_t)n1 * 128];
        uint4 u;
        u.x = pk(k0[d], k0[d + 1]); u.y = pk(k0[d + 8], k0[d + 9]);
        u.z = pk(k1[d], k1[d + 1]); u.w = pk(k1[d + 8], k1[d + 9]);
        g_Kh2[(size_t)b * 1024 + idx] = u;
    }
    for (int idx = tid; idx < 1024; idx += 256) {   // V paired frags
        int kk = idx >> 8, dtp = (idx >> 5) & 7, lane = idx & 31;
        int g = lane >> 2, t = lane & 3;
        int k0 = b * 64 + 16 * kk + 2 * t;
        int dim0 = 16 * dtp + g, dim1 = dim0 + 8;
        uint4 u;
        u.x = pk(g_V[(size_t)k0 * 128 + dim0],       g_V[(size_t)(k0 + 1) * 128 + dim0]);
        u.y = pk(g_V[(size_t)(k0 + 8) * 128 + dim0], g_V[(size_t)(k0 + 9) * 128 + dim0]);
        u.z = pk(g_V[(size_t)k0 * 128 + dim1],       g_V[(size_t)(k0 + 1) * 128 + dim1]);
        u.w = pk(g_V[(size_t)(k0 + 8) * 128 + dim1], g_V[(size_t)(k0 + 9) * 128 + dim1]);
        g_Vp[(size_t)b * 1024 + idx] = u;
    }
}

// ---------------- Kernel 3: rowmax sweep (cheap S, adj stream) --------------
#define RM_SMEM (2 * 16384)
__global__ __launch_bounds__(256, 1) void rowmax_kernel(const int* __restrict__ adj)
{
    extern __shared__ __align__(16) unsigned char smraw[];
    const int tid = threadIdx.x, w = tid >> 5, lane = tid & 31;
    const int g = lane >> 2, t = lane & 3;
    const int qrow0 = blockIdx.x * 128;
    const int r0 = qrow0 + w * 16 + g, r1 = r0 + 8;
    const int grp = blockIdx.x * 8 + w;
    const uint32_t smb = smem_u32(smraw);

#pragma unroll
    for (int i = 0; i < 4; i++) {
        int o = (tid + i * 256) * 16;
        cpa16(smb + o, (const unsigned char*)g_Kh2 + o);
    }
    CPA_COMMIT();
#pragma unroll
    for (int i = 0; i < 4; i++) {
        int o = (tid + i * 256) * 16;
        cpa16(smb + 16384 + o, (const unsigned char*)(g_Kh2 + 1024) + o);
    }
    CPA_COMMIT();

    uint32_t qh[8][4];
#pragma unroll
    for (int kk = 0; kk < 8; kk++) {
        int c = kk * 16 + 2 * t;
        qh[kk][0] = *(const uint32_t*)&g_Qh[(size_t)r0 * 128 + c];
        qh[kk][1] = *(const uint32_t*)&g_Qh[(size_t)r1 * 128 + c];
        qh[kk][2] = *(const uint32_t*)&g_Qh[(size_t)r0 * 128 + c + 8];
        qh[kk][3] = *(const uint32_t*)&g_Qh[(size_t)r1 * 128 + c + 8];
    }
    float gm0 = -3e38f, gm1 = -3e38f;

    for (int it = 0; it < 256; ++it) {
        CPA_WAIT1();
        __syncthreads();
        const uint4* ksm = (const uint4*)(smraw + (it & 1) * 16384);

        int2 a0[8], a1[8];
        const int* ar0 = adj + (size_t)r0 * NN + it * 64;
        const int* ar1 = adj + (size_t)r1 * NN + it * 64;
#pragma unroll
        for (int j = 0; j < 8; j++) {
            a0[j] = *(const int2*)&ar0[8 * j + 2 * t];
            a1[j] = *(const int2*)&ar1[8 * j + 2 * t];
        }
        float s[8][4];
#pragma unroll
        for (int j = 0; j < 8; j++)
#pragma unroll
            for (int i = 0; i < 4; i++) s[j][i] = 0.f;
#pragma unroll
        for (int kk = 0; kk < 8; kk++) {
#pragma unroll
            for (int jp = 0; jp < 4; jp++) {
                uint4 b = ksm[((kk << 2) + jp) * 32 + lane];
                MMA4(s[2 * jp],     qh[kk], b.x, b.y);
                MMA4(s[2 * jp + 1], qh[kk], b.z, b.w);
            }
        }
        float bx0 = -3e38f, bx1 = -3e38f;
#pragma unroll
        for (int j = 0; j < 8; j++) {
            bx0 = fmaxf(bx0, fmaxf(a0[j].x ? s[j][0] : -3e38f, a0[j].y ? s[j][1] : -3e38f));
            bx1 = fmaxf(bx1, fmaxf(a1[j].x ? s[j][2] : -3e38f, a1[j].y ? s[j][3] : -3e38f));
        }
        gm0 = fmaxf(gm0, bx0);
        gm1 = fmaxf(gm1, bx1);
        bx0 = fmaxf(bx0, __shfl_xor_sync(0xffffffffu, bx0, 1));
        bx0 = fmaxf(bx0, __shfl_xor_sync(0xffffffffu, bx0, 2));
        bx1 = fmaxf(bx1, __shfl_xor_sync(0xffffffffu, bx1, 1));
        bx1 = fmaxf(bx1, __shfl_xor_sync(0xffffffffu, bx1, 2));
        if (t == 0) {
            g_Bmax[(size_t)grp * 4096 + it * 16 + g]     = __float2half_rn(fmaxf(bx0, ALPHA * bx0));
            g_Bmax[(size_t)grp * 4096 + it * 16 + g + 8] = __float2half_rn(fmaxf(bx1, ALPHA * bx1));
        }
        __syncthreads();
        if (it + 2 < 256) {
            const unsigned char* src = (const unsigned char*)(g_Kh2 + (size_t)(it + 2) * 1024);
            uint32_t dst = smb + (uint32_t)(it & 1) * 16384;
#pragma unroll
            for (int i = 0; i < 4; i++) {
                int o = (tid + i * 256) * 16;
                cpa16(dst + o, src + o);
            }
        }
        CPA_COMMIT();
    }
    gm0 = fmaxf(gm0, __shfl_xor_sync(0xffffffffu, gm0, 1));
    gm0 = fmaxf(gm0, __shfl_xor_sync(0xffffffffu, gm0, 2));
    gm1 = fmaxf(gm1, __shfl_xor_sync(0xffffffffu, gm1, 1));
    gm1 = fmaxf(gm1, __shfl_xor_sync(0xffffffffu, gm1, 2));
    if (t == 0) {
        g_M[r0] = fmaxf(gm0, ALPHA * gm0);
        g_M[r1] = fmaxf(gm1, ALPHA * gm1);
    }
}

// ---------------- Kernel 4: sparse attention (skip inactive blocks) ---------
__global__ __launch_bounds__(256, 1) void attn_kernel(
    const int* __restrict__ adj, float* __restrict__ out)
{
    const int tid = threadIdx.x, w = tid >> 5, lane = tid & 31;
    const int g = lane >> 2, t = lane & 3;
    const int qrow0 = blockIdx.x * 128;
    const int r0 = qrow0 + w * 16 + g, r1 = r0 + 8;
    const int grp = blockIdx.x * 8 + w;

    uint32_t qh[8][4], ql[8][4];
#pragma unroll
    for (int kk = 0; kk < 8; kk++) {
        int c = kk * 16 + 2 * t;
        qh[kk][0] = *(const uint32_t*)&g_Qh[(size_t)r0 * 128 + c];
        qh[kk][1] = *(const uint32_t*)&g_Qh[(size_t)r1 * 128 + c];
        qh[kk][2] = *(const uint32_t*)&g_Qh[(size_t)r0 * 128 + c + 8];
        qh[kk][3] = *(const uint32_t*)&g_Qh[(size_t)r1 * 128 + c + 8];
        ql[kk][0] = *(const uint32_t*)&g_Ql[(size_t)r0 * 128 + c];
        ql[kk][1] = *(const uint32_t*)&g_Ql[(size_t)r1 * 128 + c];
        ql[kk][2] = *(const uint32_t*)&g_Ql[(size_t)r0 * 128 + c + 8];
        ql[kk][3] = *(const uint32_t*)&g_Ql[(size_t)r1 * 128 + c + 8];
    }
    const float m0 = g_M[r0], m1 = g_M[r1];
    const float n0s = m0 * LOG2E, n1s = m1 * LOG2E;

    // per-warp 256-bit activity bitmap
    uint32_t act[8];
    {
        float thr[16];
#pragma unroll
        for (int r = 0; r < 16; r++) thr[r] = g_M[grp * 16 + r] - THRD;
        const __half* bmx = g_Bmax + (size_t)grp * 4096;
#pragma unroll
        for (int c = 0; c < 8; c++) {
            int blk = 32 * c + lane;
            uint32_t uw[8];
            *(uint4*)uw       = *(const uint4*)&bmx[blk * 16];
            *(uint4*)(uw + 4) = *(const uint4*)&bmx[blk * 16 + 8];
            bool a = false;
#pragma unroll
            for (int i = 0; i < 8; i++) {
                float2 p = __half22float2(*(const __half2*)&uw[i]);
                a = a || (p.x > thr[2 * i]) || (p.y > thr[2 * i + 1]);
            }
            act[c] = __ballot_sync(0xffffffffu, a);
        }
    }

    float o[16][4];
#pragma unroll
    for (int dt = 0; dt < 16; dt++)
#pragma unroll
        for (int i = 0; i < 4; i++) o[dt][i] = 0.f;
    float l0 = 0.f, l1 = 0.f;

    for (int it = 0; it < 256; ++it) {
        if (!((act[it >> 5] >> (it & 31)) & 1u)) continue;

        const uint4* kb = g_Kp + (size_t)it * 2048;
        const uint4* vb = g_Vp + (size_t)it * 1024;
        int2 a0[8], a1[8];
        const int* ar0 = adj + (size_t)r0 * NN + it * 64;
        const int* ar1 = adj + (size_t)r1 * NN + it * 64;
#pragma unroll
        for (int j = 0; j < 8; j++) {
            a0[j] = *(const int2*)&ar0[8 * j + 2 * t];
            a1[j] = *(const int2*)&ar1[8 * j + 2 * t];
        }

        float s[8][4];
#pragma unroll
        for (int j = 0; j < 8; j++)
#pragma unroll
            for (int i = 0; i < 4; i++) s[j][i] = 0.f;
#pragma unroll
        for (int kk = 0; kk < 8; kk++) {
#pragma unroll
            for (int j = 0; j < 8; j++) {
                uint4 b = kb[((kk << 3) + j) * 32 + lane];
                MMA4(s[j], qh[kk], b.x, b.y);
                MMA4(s[j], ql[kk], b.x, b.y);
                MMA4(s[j], qh[kk], b.z, b.w);
            }
        }
#pragma unroll
        for (int j = 0; j < 8; j++) {
            float v;
            v = s[j][0]; v = fmaxf(v, ALPHA * v); s[j][0] = a0[j].x ? v : -3e38f;
            v = s[j][1]; v = fmaxf(v, ALPHA * v); s[j][1] = a0[j].y ? v : -3e38f;
            v = s[j][2]; v = fmaxf(v, ALPHA * v); s[j][2] = a1[j].x ? v : -3e38f;
            v = s[j][3]; v = fmaxf(v, ALPHA * v); s[j][3] = a1[j].y ? v : -3e38f;
        }

        uint32_t pf[4][4];
        float ps0 = 0.f, ps1 = 0.f;
#pragma unroll
        for (int kk = 0; kk < 4; kk++) {
#pragma unroll
            for (int half = 0; half < 2; half++) {
                int j = 2 * kk + half;
                float p0 = ex2f(fmaf(s[j][0], LOG2E, -n0s));
                float p1 = ex2f(fmaf(s[j][1], LOG2E, -n0s));
                float p2 = ex2f(fmaf(s[j][2], LOG2E, -n1s));
                float p3 = ex2f(fmaf(s[j][3], LOG2E, -n1s));
                __half2 hA = __floats2half2_rn(p0, p1);
                __half2 hB = __floats2half2_rn(p2, p3);
                pf[kk][0 + 2 * half] = h2u(hA);
                pf[kk][1 + 2 * half] = h2u(hB);
                float2 fA = __half22float2(hA), fB = __half22float2(hB);
                ps0 += fA.x + fA.y;
                ps1 += fB.x + fB.y;
            }
        }
        l0 += ps0;
        l1 += ps1;
#pragma unroll
        for (int kk = 0; kk < 4; kk++) {
#pragma unroll
            for (int dtp = 0; dtp < 8; dtp++) {
                uint4 v = vb[((kk << 3) + dtp) * 32 + lane];
                MMA4(o[2 * dtp],     pf[kk], v.x, v.y);
                MMA4(o[2 * dtp + 1], pf[kk], v.z, v.w);
            }
        }
    }

    l0 += __shfl_xor_sync(0xffffffffu, l0, 1);
    l0 += __shfl_xor_sync(0xffffffffu, l0, 2);
    l1 += __shfl_xor_sync(0xffffffffu, l1, 1);
    l1 += __shfl_xor_sync(0xffffffffu, l1, 2);
    const float i0 = 1.f / l0, i1 = 1.f / l1;
#pragma unroll
    for (int dt = 0; dt < 16; dt++) {
        float x0 = o[dt][0] * i0, x1 = o[dt][1] * i0;
        float x2 = o[dt][2] * i1, x3 = o[dt][3] * i1;
        x0 = (x0 > 0.f) ? x0 : (__expf(x0) - 1.f);
        x1 = (x1 > 0.f) ? x1 : (__expf(x1) - 1.f);
        x2 = (x2 > 0.f) ? x2 : (__expf(x2) - 1.f);
        x3 = (x3 > 0.f) ? x3 : (__expf(x3) - 1.f);
        int c = 8 * dt + 2 * t;
        *(float2*)&out[(size_t)r0 * 128 + c] = make_float2(x0, x1);
        *(float2*)&out[(size_t)r1 * 128 + c] = make_float2(x2, x3);
    }
}

// ---------------------------------------------------------------------------
extern "C" void kernel_launch(void* const* d_in, const int* in_sizes, int n_in,
                              void* d_out, int out_size)
{
    const float* h   = (const float*)d_in[0];
    const int*   adj = (const int*)  d_in[1];
    const float* Wq  = (const float*)d_in[2];
    const float* Wk  = (const float*)d_in[3];
    const float* Wv  = (const float*)d_in[4];
    float*       out = (float*)d_out;
    (void)in_sizes; (void)n_in; (void)out_size;

    cudaFuncSetAttribute(qkv_kernel,    cudaFuncAttributeMaxDynamicSharedMemorySize, QKV_SMEM);
    cudaFuncSetAttribute(rowmax_kernel, cudaFuncAttributeMaxDynamicSharedMemorySize, RM_SMEM);

    qkv_kernel<<<NN / 64, 256, QKV_SMEM>>>(h, Wq, Wk, Wv);
    pack_kernel<<<256, 256>>>();
    rowmax_kernel<<<NN / 128, 256, RM_SMEM>>>(adj);
    attn_kernel<<<NN / 128, 256>>>(adj, out);
}